// round 2
// baseline (speedup 1.0000x reference)
#include <cuda_runtime.h>
#include <cuda_bf16.h>

#define N_ 16384
#define T_ 60
#define M_ 8
#define K_ 2
#define LOG_2PI 1.8378770664093453f

#define BLK 128
#define ITEMS (N_ * T_)          // 983040
#define GRID (ITEMS / BLK)       // 7680 (exact)

// Device-global scratch (zero-initialized at module load; self-reset by the
// finalizing block so every graph replay starts clean).
__device__ double g_num[T_];
__device__ double g_den[T_];
__device__ unsigned int g_ticket;

__global__ __launch_bounds__(BLK) void nll_fused_kernel(
    const float* __restrict__ mu,
    const float* __restrict__ sigma,
    const float* __restrict__ pi,
    const float* __restrict__ x,
    const float* __restrict__ mask,
    float* __restrict__ out)
{
    // Padded smem: sigma rows 9 float4 (8 used), mu rows 5 float4 (4 used).
    // Per 8-lane LDS.128 phase, banks (36i+4c)%32 / (20i+4c)%32 are distinct
    // -> conflict-free shared reads.
    __shared__ float4 s_sig[BLK * 9];
    __shared__ float4 s_mu [BLK * 5];
    __shared__ float  s_num[T_];
    __shared__ float  s_den[T_];
    __shared__ unsigned int s_last;

    const int tid  = threadIdx.x;
    const int base = blockIdx.x * BLK;

    // ---- Coalesced global->shared staging (consecutive lanes -> consecutive
    // float4 -> 4 cache lines per warp request) ----
    const float4* gs = reinterpret_cast<const float4*>(sigma) + (size_t)base * 8;
    #pragma unroll
    for (int j = 0; j < 8; j++) {
        int w = j * BLK + tid;
        s_sig[(w >> 3) * 9 + (w & 7)] = gs[w];
    }
    const float4* gm = reinterpret_cast<const float4*>(mu) + (size_t)base * 4;
    #pragma unroll
    for (int j = 0; j < 4; j++) {
        int w = j * BLK + tid;
        s_mu[(w >> 2) * 5 + (w & 3)] = gm[w];
    }
    if (tid < T_) { s_num[tid] = 0.0f; s_den[tid] = 0.0f; }

    // Direct (naturally coalesced) small loads
    const int idx = base + tid;                 // idx = n*T + t
    const int n   = idx / T_;
    const int t   = idx - n * T_;
    float2 xv = reinterpret_cast<const float2*>(x)[idx];
    float  mk = mask[idx];
    float4 pa = __ldg(reinterpret_cast<const float4*>(pi) + (size_t)n * 2);
    float4 pb = __ldg(reinterpret_cast<const float4*>(pi) + (size_t)n * 2 + 1);

    __syncthreads();

    // ---- Inline logZ = logsumexp(pi[n,:]) ----
    float pmx = fmaxf(fmaxf(fmaxf(pa.x, pa.y), fmaxf(pa.z, pa.w)),
                      fmaxf(fmaxf(pb.x, pb.y), fmaxf(pb.z, pb.w)));
    float ps = __expf(pa.x - pmx) + __expf(pa.y - pmx) + __expf(pa.z - pmx) + __expf(pa.w - pmx)
             + __expf(pb.x - pmx) + __expf(pb.y - pmx) + __expf(pb.z - pmx) + __expf(pb.w - pmx);
    float logZ = pmx + __logf(ps);

    // ---- Per-component closed-form 2x2 MVN log-prob (no cholesky/sqrt) ----
    const float x0 = xv.x, x1 = xv.y;
    float lp[M_];
    #pragma unroll
    for (int c = 0; c < M_ / 2; c++) {
        float4 mv = s_mu [tid * 5 + c];       // comps 2c (x,y), 2c+1 (z,w)
        float4 sA = s_sig[tid * 9 + 2 * c];   // [s00,s01,s10,s11]
        float4 sB = s_sig[tid * 9 + 2 * c + 1];
        {
            float d0 = x0 - mv.x, d1 = x1 - mv.y;
            float det  = fmaf(sA.x, sA.w, -sA.y * sA.z);
            float rdet = __frcp_rn(det);
            float quad = fmaf(d0 * d0, sA.w, fmaf(-2.0f * sA.y, d0 * d1, d1 * d1 * sA.x));
            lp[2 * c] = -LOG_2PI - 0.5f * quad * rdet - 0.5f * __logf(det);
        }
        {
            float d0 = x0 - mv.z, d1 = x1 - mv.w;
            float det  = fmaf(sB.x, sB.w, -sB.y * sB.z);
            float rdet = __frcp_rn(det);
            float quad = fmaf(d0 * d0, sB.w, fmaf(-2.0f * sB.y, d0 * d1, d1 * d1 * sB.x));
            lp[2 * c + 1] = -LOG_2PI - 0.5f * quad * rdet - 0.5f * __logf(det);
        }
    }
    lp[0] += pa.x; lp[1] += pa.y; lp[2] += pa.z; lp[3] += pa.w;
    lp[4] += pb.x; lp[5] += pb.y; lp[6] += pb.z; lp[7] += pb.w;

    float mx = lp[0];
    #pragma unroll
    for (int m = 1; m < M_; m++) mx = fmaxf(mx, lp[m]);
    float s = 0.0f;
    #pragma unroll
    for (int m = 0; m < M_; m++) s += __expf(lp[m] - mx);

    float loss = -(mx + __logf(s) - logZ);

    atomicAdd(&s_num[t], loss * mk);
    atomicAdd(&s_den[t], mk);
    __syncthreads();

    if (tid < T_) {
        atomicAdd(&g_num[tid], (double)s_num[tid]);
        atomicAdd(&g_den[tid], (double)s_den[tid]);
    }

    // ---- Last-block finalize (ticket pattern), then self-reset for replay ----
    __threadfence();
    if (tid == 0) s_last = atomicAdd(&g_ticket, 1u);
    __syncthreads();

    if (s_last == (unsigned int)(gridDim.x - 1)) {
        __threadfence();
        double v = 0.0;
        if (tid < T_) v = g_num[tid] / g_den[tid];
        // reduce over warps 0 and 1 (tid < 64 covers all T_=60 lanes)
        #pragma unroll
        for (int off = 16; off > 0; off >>= 1)
            v += __shfl_down_sync(0xFFFFFFFFu, v, off);
        __shared__ double partial[2];
        if (tid == 0)  partial[0] = v;
        if (tid == 32) partial[1] = v;
        __syncthreads();
        if (tid == 0) out[0] = (float)(partial[0] + partial[1]);
        // reset scratch for the next graph replay
        if (tid < T_) { g_num[tid] = 0.0; g_den[tid] = 0.0; }
        if (tid == 0) g_ticket = 0u;
    }
}

extern "C" void kernel_launch(void* const* d_in, const int* in_sizes, int n_in,
                              void* d_out, int out_size) {
    const float* mu    = (const float*)d_in[0];
    const float* sigma = (const float*)d_in[1];
    const float* pi    = (const float*)d_in[2];
    const float* x     = (const float*)d_in[3];
    const float* mask  = (const float*)d_in[4];
    float* out = (float*)d_out;

    nll_fused_kernel<<<GRID, BLK>>>(mu, sigma, pi, x, mask, out);
}

// round 3
// speedup vs baseline: 1.7636x; 1.7636x over previous
#include <cuda_runtime.h>
#include <cuda_bf16.h>

#define N_ 16384
#define T_ 60
#define M_ 8
#define K_ 2
#define LOG_2PI 1.8378770664093453f

#define BLK 128
#define ITEMS (N_ * T_)          // 983040
#define GRID (ITEMS / BLK)       // 7680 (exact)
#define NSLOT 128                // spread slots per timestep (kills atomic contention)

// Device-global scratch (zero-initialized at load; self-reset by the final
// block so every graph replay starts clean).
__device__ float g_accn[T_ * NSLOT];
__device__ float g_accd[T_ * NSLOT];
__device__ unsigned int g_ticket;

__global__ __launch_bounds__(BLK) void nll_fused_kernel(
    const float* __restrict__ mu,
    const float* __restrict__ sigma,
    const float* __restrict__ pi,
    const float* __restrict__ x,
    const float* __restrict__ mask,
    float* __restrict__ out)
{
    // Padded smem: sigma rows 9 float4 (8 used), mu rows 5 float4 (4 used).
    // Per 8-lane LDS.128 phase banks are distinct -> conflict-free.
    __shared__ float4 s_sig[BLK * 9];
    __shared__ float4 s_mu [BLK * 5];
    __shared__ float  s_num[T_];
    __shared__ float  s_den[T_];
    __shared__ unsigned int s_last;

    const int tid  = threadIdx.x;
    const int base = blockIdx.x * BLK;

    // ---- Coalesced global->shared staging ----
    const float4* gs = reinterpret_cast<const float4*>(sigma) + (size_t)base * 8;
    #pragma unroll
    for (int j = 0; j < 8; j++) {
        int w = j * BLK + tid;
        s_sig[(w >> 3) * 9 + (w & 7)] = gs[w];
    }
    const float4* gm = reinterpret_cast<const float4*>(mu) + (size_t)base * 4;
    #pragma unroll
    for (int j = 0; j < 4; j++) {
        int w = j * BLK + tid;
        s_mu[(w >> 2) * 5 + (w & 3)] = gm[w];
    }
    if (tid < T_) { s_num[tid] = 0.0f; s_den[tid] = 0.0f; }

    const int idx = base + tid;                 // idx = n*T + t
    const int n   = idx / T_;
    const int t   = idx - n * T_;
    float2 xv = reinterpret_cast<const float2*>(x)[idx];
    float  mk = mask[idx];
    float4 pa = __ldg(reinterpret_cast<const float4*>(pi) + (size_t)n * 2);
    float4 pb = __ldg(reinterpret_cast<const float4*>(pi) + (size_t)n * 2 + 1);

    __syncthreads();

    // ---- Inline logZ = logsumexp(pi[n,:]) ----
    float pmx = fmaxf(fmaxf(fmaxf(pa.x, pa.y), fmaxf(pa.z, pa.w)),
                      fmaxf(fmaxf(pb.x, pb.y), fmaxf(pb.z, pb.w)));
    float ps = __expf(pa.x - pmx) + __expf(pa.y - pmx) + __expf(pa.z - pmx) + __expf(pa.w - pmx)
             + __expf(pb.x - pmx) + __expf(pb.y - pmx) + __expf(pb.z - pmx) + __expf(pb.w - pmx);
    float logZ = pmx + __logf(ps);

    // ---- Closed-form 2x2 MVN log-prob per component ----
    const float x0 = xv.x, x1 = xv.y;
    float lp[M_];
    #pragma unroll
    for (int c = 0; c < M_ / 2; c++) {
        float4 mv = s_mu [tid * 5 + c];
        float4 sA = s_sig[tid * 9 + 2 * c];
        float4 sB = s_sig[tid * 9 + 2 * c + 1];
        {
            float d0 = x0 - mv.x, d1 = x1 - mv.y;
            float det  = fmaf(sA.x, sA.w, -sA.y * sA.z);
            float rdet = __frcp_rn(det);
            float quad = fmaf(d0 * d0, sA.w, fmaf(-2.0f * sA.y, d0 * d1, d1 * d1 * sA.x));
            lp[2 * c] = -LOG_2PI - 0.5f * quad * rdet - 0.5f * __logf(det);
        }
        {
            float d0 = x0 - mv.z, d1 = x1 - mv.w;
            float det  = fmaf(sB.x, sB.w, -sB.y * sB.z);
            float rdet = __frcp_rn(det);
            float quad = fmaf(d0 * d0, sB.w, fmaf(-2.0f * sB.y, d0 * d1, d1 * d1 * sB.x));
            lp[2 * c + 1] = -LOG_2PI - 0.5f * quad * rdet - 0.5f * __logf(det);
        }
    }
    lp[0] += pa.x; lp[1] += pa.y; lp[2] += pa.z; lp[3] += pa.w;
    lp[4] += pb.x; lp[5] += pb.y; lp[6] += pb.z; lp[7] += pb.w;

    float mx = lp[0];
    #pragma unroll
    for (int m = 1; m < M_; m++) mx = fmaxf(mx, lp[m]);
    float s = 0.0f;
    #pragma unroll
    for (int m = 0; m < M_; m++) s += __expf(lp[m] - mx);

    float loss = -(mx + __logf(s) - logZ);

    atomicAdd(&s_num[t], loss * mk);
    atomicAdd(&s_den[t], mk);
    __syncthreads();

    // ---- Spread global accumulation: contention = GRID/NSLOT = 60 per addr ----
    const int slot = blockIdx.x & (NSLOT - 1);
    if (tid < T_) {
        atomicAdd(&g_accn[tid * NSLOT + slot], s_num[tid]);
        atomicAdd(&g_accd[tid * NSLOT + slot], s_den[tid]);
    }

    // ---- Last-block finalize (ticket), then self-reset for replay ----
    __threadfence();
    if (tid == 0) s_last = atomicAdd(&g_ticket, 1u);
    __syncthreads();

    if (s_last == (unsigned int)(gridDim.x - 1)) {
        __threadfence();
        double v = 0.0;
        if (tid < T_) {
            const float4* pn = reinterpret_cast<const float4*>(g_accn + tid * NSLOT);
            const float4* pd = reinterpret_cast<const float4*>(g_accd + tid * NSLOT);
            double num = 0.0, den = 0.0;
            #pragma unroll 8
            for (int j = 0; j < NSLOT / 4; j++) {
                float4 a = pn[j];
                float4 b = pd[j];
                num += (double)a.x + (double)a.y + (double)a.z + (double)a.w;
                den += (double)b.x + (double)b.y + (double)b.z + (double)b.w;
            }
            v = num / den;
        }
        #pragma unroll
        for (int off = 16; off > 0; off >>= 1)
            v += __shfl_down_sync(0xFFFFFFFFu, v, off);
        __shared__ double partial[2];
        if (tid == 0)  partial[0] = v;
        if (tid == 32) partial[1] = v;
        __syncthreads();
        if (tid == 0) out[0] = (float)(partial[0] + partial[1]);
        // reset scratch for the next graph replay (reads above are complete:
        // they are ordered before the __syncthreads we just passed)
        for (int i = tid; i < T_ * NSLOT; i += BLK) {
            g_accn[i] = 0.0f;
            g_accd[i] = 0.0f;
        }
        if (tid == 0) g_ticket = 0u;
    }
}

extern "C" void kernel_launch(void* const* d_in, const int* in_sizes, int n_in,
                              void* d_out, int out_size) {
    const float* mu    = (const float*)d_in[0];
    const float* sigma = (const float*)d_in[1];
    const float* pi    = (const float*)d_in[2];
    const float* x     = (const float*)d_in[3];
    const float* mask  = (const float*)d_in[4];
    float* out = (float*)d_out;

    nll_fused_kernel<<<GRID, BLK>>>(mu, sigma, pi, x, mask, out);
}

// round 6
// speedup vs baseline: 2.0425x; 1.1581x over previous
#include <cuda_runtime.h>
#include <cuda_bf16.h>
#include <cstdint>

#define N_ 16384
#define T_ 60
#define M_ 8
#define K_ 2
#define LOG_2PI 1.8378770664093453f

#define BLK 128
#define ITEMS (N_ * T_)          // 983040
#define GRID (ITEMS / BLK)       // 7680 (exact)
#define NSLOT 128                // spread slots per timestep

// Device-global scratch (zero-init at load; self-reset by the final block).
__device__ float g_accn[T_ * NSLOT];
__device__ float g_accd[T_ * NSLOT];
__device__ unsigned int g_ticket;

__device__ __forceinline__ void cp_async16(unsigned int smem_addr, const void* gptr) {
    asm volatile("cp.async.cg.shared.global [%0], [%1], 16;\n"
                 :: "r"(smem_addr), "l"(gptr));
}

__global__ __launch_bounds__(BLK, 10) void nll_fused_kernel(
    const float* __restrict__ mu,
    const float* __restrict__ sigma,
    const float* __restrict__ pi,
    const float* __restrict__ x,
    const float* __restrict__ mask,
    float* __restrict__ out)
{
    // Padded smem: sigma rows 9 float4 (8 used), mu rows 5 float4 (4 used)
    // -> conflict-free LDS.128 on the compute side.
    __shared__ float4 s_sig[BLK * 9];
    __shared__ float4 s_mu [BLK * 5];
    __shared__ float  s_num[T_];
    __shared__ float  s_den[T_];
    __shared__ unsigned int s_last;

    const int tid  = threadIdx.x;
    const int base = blockIdx.x * BLK;

    // ---- Register-free coalesced staging via cp.async (LDGSTS) ----
    const float4* gs = reinterpret_cast<const float4*>(sigma) + (size_t)base * 8;
    unsigned int sig_b = (unsigned int)__cvta_generic_to_shared(s_sig);
    #pragma unroll
    for (int j = 0; j < 8; j++) {
        int w = j * BLK + tid;
        cp_async16(sig_b + (unsigned int)(((w >> 3) * 9 + (w & 7)) * 16), gs + w);
    }
    const float4* gm = reinterpret_cast<const float4*>(mu) + (size_t)base * 4;
    unsigned int mu_b = (unsigned int)__cvta_generic_to_shared(s_mu);
    #pragma unroll
    for (int j = 0; j < 4; j++) {
        int w = j * BLK + tid;
        cp_async16(mu_b + (unsigned int)(((w >> 2) * 5 + (w & 3)) * 16), gm + w);
    }
    asm volatile("cp.async.commit_group;\n");

    if (tid < T_) { s_num[tid] = 0.0f; s_den[tid] = 0.0f; }

    // Independent small loads overlap the bulk transfer
    const int idx = base + tid;                 // idx = n*T + t
    const int n   = idx / T_;
    const int t   = idx - n * T_;
    float2 xv = reinterpret_cast<const float2*>(x)[idx];
    float  mk = mask[idx];
    float4 pa = __ldg(reinterpret_cast<const float4*>(pi) + (size_t)n * 2);
    float4 pb = __ldg(reinterpret_cast<const float4*>(pi) + (size_t)n * 2 + 1);

    // ---- logZ = logsumexp(pi[n,:]) (compute while cp.async drains) ----
    float pmx = fmaxf(fmaxf(fmaxf(pa.x, pa.y), fmaxf(pa.z, pa.w)),
                      fmaxf(fmaxf(pb.x, pb.y), fmaxf(pb.z, pb.w)));
    float ps = __expf(pa.x - pmx) + __expf(pa.y - pmx) + __expf(pa.z - pmx) + __expf(pa.w - pmx)
             + __expf(pb.x - pmx) + __expf(pb.y - pmx) + __expf(pb.z - pmx) + __expf(pb.w - pmx);
    float logZ = pmx + __logf(ps);

    asm volatile("cp.async.wait_group 0;\n" ::: "memory");
    __syncthreads();

    // ---- Closed-form 2x2 MVN log-prob per component ----
    const float x0 = xv.x, x1 = xv.y;
    float lp[M_];
    #pragma unroll
    for (int c = 0; c < M_ / 2; c++) {
        float4 mv = s_mu [tid * 5 + c];
        float4 sA = s_sig[tid * 9 + 2 * c];
        float4 sB = s_sig[tid * 9 + 2 * c + 1];
        {
            float d0 = x0 - mv.x, d1 = x1 - mv.y;
            float det  = fmaf(sA.x, sA.w, -sA.y * sA.z);
            float rdet = __frcp_rn(det);
            float quad = fmaf(d0 * d0, sA.w, fmaf(-2.0f * sA.y, d0 * d1, d1 * d1 * sA.x));
            lp[2 * c] = -LOG_2PI - 0.5f * quad * rdet - 0.5f * __logf(det);
        }
        {
            float d0 = x0 - mv.z, d1 = x1 - mv.w;
            float det  = fmaf(sB.x, sB.w, -sB.y * sB.z);
            float rdet = __frcp_rn(det);
            float quad = fmaf(d0 * d0, sB.w, fmaf(-2.0f * sB.y, d0 * d1, d1 * d1 * sB.x));
            lp[2 * c + 1] = -LOG_2PI - 0.5f * quad * rdet - 0.5f * __logf(det);
        }
    }
    lp[0] += pa.x; lp[1] += pa.y; lp[2] += pa.z; lp[3] += pa.w;
    lp[4] += pb.x; lp[5] += pb.y; lp[6] += pb.z; lp[7] += pb.w;

    float mx = lp[0];
    #pragma unroll
    for (int m = 1; m < M_; m++) mx = fmaxf(mx, lp[m]);
    float s = 0.0f;
    #pragma unroll
    for (int m = 0; m < M_; m++) s += __expf(lp[m] - mx);

    float loss = -(mx + __logf(s) - logZ);

    atomicAdd(&s_num[t], loss * mk);
    atomicAdd(&s_den[t], mk);
    __syncthreads();

    // ---- Spread global accumulation (GRID/NSLOT = 60 blocks per address) ----
    const int slot = blockIdx.x & (NSLOT - 1);
    if (tid < T_) {
        atomicAdd(&g_accn[tid * NSLOT + slot], s_num[tid]);
        atomicAdd(&g_accd[tid * NSLOT + slot], s_den[tid]);
    }

    // ---- Last-block finalize (ticket), then self-reset for replay ----
    __threadfence();
    if (tid == 0) s_last = atomicAdd(&g_ticket, 1u);
    __syncthreads();

    if (s_last == (unsigned int)(gridDim.x - 1)) {
        __threadfence();
        double v = 0.0;
        if (tid < T_) {
            const float4* pn = reinterpret_cast<const float4*>(g_accn + tid * NSLOT);
            const float4* pd = reinterpret_cast<const float4*>(g_accd + tid * NSLOT);
            double num = 0.0, den = 0.0;
            #pragma unroll 8
            for (int j = 0; j < NSLOT / 4; j++) {
                float4 a = pn[j];
                float4 b = pd[j];
                num += (double)a.x + (double)a.y + (double)a.z + (double)a.w;
                den += (double)b.x + (double)b.y + (double)b.z + (double)b.w;
            }
            v = num / den;
        }
        #pragma unroll
        for (int off = 16; off > 0; off >>= 1)
            v += __shfl_down_sync(0xFFFFFFFFu, v, off);
        __shared__ double partial[2];
        if (tid == 0)  partial[0] = v;
        if (tid == 32) partial[1] = v;
        __syncthreads();
        if (tid == 0) out[0] = (float)(partial[0] + partial[1]);
        for (int i = tid; i < T_ * NSLOT; i += BLK) {
            g_accn[i] = 0.0f;
            g_accd[i] = 0.0f;
        }
        if (tid == 0) g_ticket = 0u;
    }
}

extern "C" void kernel_launch(void* const* d_in, const int* in_sizes, int n_in,
                              void* d_out, int out_size) {
    const float* mu    = (const float*)d_in[0];
    const float* sigma = (const float*)d_in[1];
    const float* pi    = (const float*)d_in[2];
    const float* x     = (const float*)d_in[3];
    const float* mask  = (const float*)d_in[4];
    float* out = (float*)d_out;

    nll_fused_kernel<<<GRID, BLK>>>(mu, sigma, pi, x, mask, out);
}